// round 7
// baseline (speedup 1.0000x reference)
#include <cuda_runtime.h>
#include <math.h>

#define BATCH 512
#define TT 5
#define NPROB (BATCH*TT)

// ---------------- scratch (device globals: no allocation allowed) ----------------
__device__ float g_h1[BATCH*10*20*20];   // conv1+pool output
__device__ float g_h2[BATCH*320];        // conv2+pool output (flattened)
__device__ float g_pr[BATCH*20];
__device__ float g_v[BATCH*40];
__device__ __align__(16) float g_wT[118000];  // transposed weights

// ================= packed f32x2 helpers =================
typedef unsigned long long u64;
__device__ __forceinline__ u64 mkf2(float lo, float hi){ u64 r; asm("mov.b64 %0,{%1,%2};":"=l"(r):"f"(lo),"f"(hi)); return r; }
__device__ __forceinline__ float2 unf2(u64 v){ float2 p; asm("mov.b64 {%0,%1},%2;":"=f"(p.x),"=f"(p.y):"l"(v)); return p; }
__device__ __forceinline__ u64 f2fma(u64 a,u64 b,u64 c){ u64 d; asm("fma.rn.f32x2 %0,%1,%2,%3;":"=l"(d):"l"(a),"l"(b),"l"(c)); return d; }
__device__ __forceinline__ u64 f2add(u64 a,u64 b){ u64 d; asm("add.rn.f32x2 %0,%1,%2;":"=l"(d):"l"(a),"l"(b)); return d; }
__device__ __forceinline__ u64 f2mul(u64 a,u64 b){ u64 d; asm("mul.rn.f32x2 %0,%1,%2;":"=l"(d):"l"(a),"l"(b)); return d; }

// ---------------- conv1: (B,1,50,50) -> conv 11x11 -> pool2 -> relu -> (B,10,20,20) ----
__global__ void conv1_kernel(const float* __restrict__ img,
                             const float* __restrict__ w,
                             const float* __restrict__ bias)
{
    __shared__ float sIm[2500];
    __shared__ float sW[1210];
    __shared__ float sB[10];
    int b = blockIdx.x;
    int tid = threadIdx.x;  // 0..399
    for (int i = tid; i < 2500; i += 400) sIm[i] = img[b*2500 + i];
    for (int i = tid; i < 1210; i += 400) sW[i] = w[i];
    if (tid < 10) sB[tid] = bias[tid];
    __syncthreads();

    int oy = tid / 20, ox = tid % 20;
    float acc[10][4];
#pragma unroll
    for (int c = 0; c < 10; c++) { acc[c][0]=0.f; acc[c][1]=0.f; acc[c][2]=0.f; acc[c][3]=0.f; }
    int iy0 = 2*oy, ix0 = 2*ox;
    for (int ky = 0; ky < 11; ky++) {
        const float* row0 = &sIm[(iy0+ky)*50 + ix0];
        const float* row1 = row0 + 50;
#pragma unroll
        for (int kx = 0; kx < 11; kx++) {
            float p00 = row0[kx], p01 = row0[kx+1];
            float p10 = row1[kx], p11 = row1[kx+1];
#pragma unroll
            for (int c = 0; c < 10; c++) {
                float wv = sW[c*121 + ky*11 + kx];
                acc[c][0] += wv*p00; acc[c][1] += wv*p01;
                acc[c][2] += wv*p10; acc[c][3] += wv*p11;
            }
        }
    }
#pragma unroll
    for (int c = 0; c < 10; c++) {
        float m = fmaxf(fmaxf(acc[c][0],acc[c][1]), fmaxf(acc[c][2],acc[c][3]));
        m += sB[c];
        g_h1[((b*10 + c)*20 + oy)*20 + ox] = fmaxf(m, 0.0f);
    }
}

// ---------------- conv2: (B,10,20,20) -> conv 5x5 (20 out) -> pool4 -> relu -> (B,320) ----
__global__ void conv2_kernel(const float* __restrict__ w,   // (20,10,5,5)
                             const float* __restrict__ bias)
{
    __shared__ __align__(16) float sm[9024];
    float* sIn = sm;          // 4000
    float* sW  = sm + 4000;   // 5000 rearranged: [ci][ky][kx][c], c contiguous (20)
    int b = blockIdx.x;
    int tid = threadIdx.x;    // 0..319
    for (int i = tid; i < 4000; i += 320) sIn[i] = g_h1[b*4000 + i];
    for (int i = tid; i < 5000; i += 320) {
        int c = i % 20;
        int r = i / 20;       // ci*25 + ky*5 + kx
        sW[i] = w[c*250 + r];
    }
    __syncthreads();

    bool active = tid < 256;
    int ix = tid & 3, iy = (tid>>2)&3, px = (tid>>4)&3, py = (tid>>6)&3;
    int Y = py*4 + iy, X = px*4 + ix;
    float acc[20];
#pragma unroll
    for (int c = 0; c < 20; c++) acc[c] = 0.0f;
    if (active) {
        for (int ci = 0; ci < 10; ci++) {
            const float* inp = &sIn[ci*400 + Y*20 + X];
#pragma unroll
            for (int ky = 0; ky < 5; ky++) {
#pragma unroll
                for (int kx = 0; kx < 5; kx++) {
                    float pix = inp[ky*20 + kx];
                    const float4* wp = (const float4*)&sW[(ci*25 + ky*5 + kx)*20];
#pragma unroll
                    for (int j = 0; j < 5; j++) {
                        float4 wv = wp[j];
                        acc[4*j+0] += wv.x*pix;
                        acc[4*j+1] += wv.y*pix;
                        acc[4*j+2] += wv.z*pix;
                        acc[4*j+3] += wv.w*pix;
                    }
                }
            }
        }
    }
    __syncthreads();
    float* sConv = sm;
    if (active) {
        int q = py*4 + px;
        int pos = iy*4 + ix;
#pragma unroll
        for (int c = 0; c < 20; c++) sConv[(c*16 + q)*16 + pos] = acc[c];
    }
    __syncthreads();
    {
        int c = tid / 16, qq = tid % 16;
        const float* p = &sConv[(c*16+qq)*16];
        float m = p[0];
#pragma unroll
        for (int k = 1; k < 16; k++) m = fmaxf(m, p[k]);
        m += bias[c];
        g_h2[b*320 + c*16 + qq] = fmaxf(m, 0.0f);
    }
}

// ---------------- weight transpose: [N][K] -> [K][N] segments into g_wT --------------
// offsets: w3T 0(48000) w4T 48000(15000) pw1T 63000(14500) vw1T 77500(14500)
//          pw2T 92000(10000) vw2T 102000(10000) pw3T 112000(2000) vw3T 114000(4000)
__global__ void transpose_w(const float* __restrict__ w3, const float* __restrict__ w4,
                            const float* __restrict__ pw1, const float* __restrict__ vw1,
                            const float* __restrict__ pw2, const float* __restrict__ vw2,
                            const float* __restrict__ pw3, const float* __restrict__ vw3)
{
    int i = blockIdx.x*blockDim.x + threadIdx.x;
    if (i >= 118000) return;
    float v;
    if (i < 48000)       { int n=i%150, k=i/150;                 v = w3[n*320+k]; }
    else if (i < 63000)  { int j=i-48000;  int n=j%100, k=j/100; v = w4[n*150+k]; }
    else if (i < 77500)  { int j=i-63000;  int n=j%100, k=j/100; v = pw1[n*145+k]; }
    else if (i < 92000)  { int j=i-77500;  int n=j%100, k=j/100; v = vw1[n*145+k]; }
    else if (i < 102000) { int j=i-92000;  int n=j%100, k=j/100; v = pw2[n*100+k]; }
    else if (i < 112000) { int j=i-102000; int n=j%100, k=j/100; v = vw2[n*100+k]; }
    else if (i < 114000) { int j=i-112000; int n=j%20,  k=j/20;  v = pw3[n*100+k]; }
    else                 { int j=i-114000; int n=j%40,  k=j/40;  v = vw3[n*100+k]; }
    g_wT[i] = v;
}

// ---------------- fused MLP: one warp per batch row, layers chained in smem -----------
// Y[n] = act( sum_k X[k] * WT[k*N+n] + bias[n] ), lanes cover 64 n's via float2 loads.
template<int N, int K, bool RELU>
__device__ __forceinline__ void layerT(const float* __restrict__ X,
                                       const float* __restrict__ WT,
                                       const float* __restrict__ bias,
                                       float* __restrict__ Y, int lane)
{
#pragma unroll
    for (int n0 = 0; n0 < N; n0 += 64) {
        int n = n0 + 2*lane;
        int nc = (n <= N-2) ? n : (N-2);   // N is even for all layers
        const float* wp = WT + nc;
        float a0 = 0.f, a1 = 0.f;
#pragma unroll 8
        for (int k = 0; k < K; k++) {
            float2 wv = *(const float2*)(wp + k*N);
            float xv = X[k];
            a0 = fmaf(xv, wv.x, a0);
            a1 = fmaf(xv, wv.y, a1);
        }
        a0 += bias[nc]; a1 += bias[nc+1];
        if (RELU) { a0 = fmaxf(a0, 0.f); a1 = fmaxf(a1, 0.f); }
        if (n < N)   Y[n]   = a0;
        if (n+1 < N) Y[n+1] = a1;
    }
}

__global__ __launch_bounds__(128) void mlp_kernel(const float* __restrict__ xtraj,
    const float* __restrict__ b3, const float* __restrict__ b4,
    const float* __restrict__ pb1, const float* __restrict__ vb1,
    const float* __restrict__ pb2, const float* __restrict__ vb2,
    const float* __restrict__ pb3, const float* __restrict__ vb3)
{
    __shared__ float sA[4][324];
    __shared__ float sB[4][204];
    int r = threadIdx.x >> 5, lane = threadIdx.x & 31;
    int row = blockIdx.x*4 + r;
    float* A  = sA[r];
    float* Bf = sB[r];

    for (int k = lane; k < 320; k += 32) A[k] = g_h2[row*320 + k];
    __syncwarp();
    layerT<150,320,true>(A, g_wT,        b3, Bf, lane);          // t150
    __syncwarp();
    layerT<100,150,true>(Bf, g_wT+48000, b4, A, lane);           // e100 -> A[0:100]
    for (int j = lane; j < 45; j += 32) A[100+j] = xtraj[row*45 + j];  // h145
    __syncwarp();
    layerT<100,145,true>(A, g_wT+63000, pb1, Bf,     lane);      // p-head L1
    layerT<100,145,true>(A, g_wT+77500, vb1, Bf+100, lane);      // v-head L1
    __syncwarp();
    layerT<100,100,true>(Bf,     g_wT+92000,  pb2, A,     lane); // p-head L2
    layerT<100,100,true>(Bf+100, g_wT+102000, vb2, A+100, lane); // v-head L2
    __syncwarp();
    layerT<20,100,false>(A,     g_wT+112000, pb3, g_pr + row*20, lane);
    layerT<40,100,false>(A+100, g_wT+114000, vb3, g_v  + row*40, lane);
}

// ---------------- PDHG solver: packed f32x2, two problems per thread -------------
struct CP {
    u64 a24,a25,a26,a27,a28,a29,a2a,a2b;
    u64 nv0,nv1,nv2,nv3,nv4,nv5;
    u64 fc0,fc1,fc2,fc3,fc4,fc5;
    u64 fe0,fe1,fe2,fe3,fe4,fe5,fe6,fe7;
    u64 M1;
};

__device__ __forceinline__ void amul2(const CP& c, const u64* s, u64* az)
{
    az[0]  = f2add(f2add(f2add(s[4],s[5]), f2add(s[6],s[7])), f2add(s[8],s[9]));
    az[1]  = f2add(s[10],s[11]);
    az[2]  = f2fma(c.a26,s[6], f2fma(c.a24,s[4], f2fma(c.a27,s[7], f2fma(c.a25,s[5],
             f2fma(c.a2a,s[10], f2fma(c.a28,s[8], f2fma(c.a2b,s[11], f2mul(c.a29,s[9]))))))));
    az[3]  = f2fma(c.nv0,s[12], f2fma(c.nv2,s[14], s[0]));
    az[4]  = f2fma(c.nv1,s[12], f2fma(c.nv3,s[14], s[2]));
    az[5]  = f2add(s[12],s[14]);
    az[6]  = f2fma(c.nv2,s[13], f2fma(c.nv4,s[15], s[1]));
    az[7]  = f2fma(c.nv3,s[13], f2fma(c.nv5,s[15], s[3]));
    az[8]  = f2add(s[13],s[15]);
    az[9]  = f2fma(c.fc0,s[16], f2fma(c.fc2,s[18], f2mul(s[4],c.M1)));
    az[10] = f2fma(c.fc1,s[16], f2fma(c.fc3,s[18], f2mul(s[6],c.M1)));
    az[11] = f2fma(c.fc2,s[17], f2fma(c.fc4,s[19], f2mul(s[5],c.M1)));
    az[12] = f2fma(c.fc3,s[17], f2fma(c.fc5,s[19], f2mul(s[7],c.M1)));
    az[13] = f2fma(c.fe0,s[20], f2fma(c.fe2,s[21], f2mul(s[8],c.M1)));
    az[14] = f2fma(c.fe1,s[20], f2fma(c.fe3,s[21], f2mul(s[10],c.M1)));
    az[15] = f2fma(c.fe4,s[22], f2fma(c.fe6,s[23], f2mul(s[9],c.M1)));
    az[16] = f2fma(c.fe5,s[22], f2fma(c.fe7,s[23], f2mul(s[11],c.M1)));
}

__device__ __forceinline__ void atmul2(const CP& c, const u64* y, u64* g)
{
    g[0]  = y[3]; g[1] = y[6]; g[2] = y[4]; g[3] = y[7];
    g[4]  = f2fma(c.a24,y[2], f2fma(y[9], c.M1, y[0]));
    g[5]  = f2fma(c.a25,y[2], f2fma(y[11],c.M1, y[0]));
    g[6]  = f2fma(c.a26,y[2], f2fma(y[10],c.M1, y[0]));
    g[7]  = f2fma(c.a27,y[2], f2fma(y[12],c.M1, y[0]));
    g[8]  = f2fma(c.a28,y[2], f2fma(y[13],c.M1, y[0]));
    g[9]  = f2fma(c.a29,y[2], f2fma(y[15],c.M1, y[0]));
    g[10] = f2fma(c.a2a,y[2], f2fma(y[14],c.M1, y[1]));
    g[11] = f2fma(c.a2b,y[2], f2fma(y[16],c.M1, y[1]));
    g[12] = f2fma(c.nv0,y[3], f2fma(c.nv1,y[4], y[5]));
    g[13] = f2fma(c.nv2,y[6], f2fma(c.nv3,y[7], y[8]));
    g[14] = f2fma(c.nv2,y[3], f2fma(c.nv3,y[4], y[5]));
    g[15] = f2fma(c.nv4,y[6], f2fma(c.nv5,y[7], y[8]));
    g[16] = f2fma(c.fc0,y[9],  f2mul(c.fc1,y[10]));
    g[17] = f2fma(c.fc2,y[11], f2mul(c.fc3,y[12]));
    g[18] = f2fma(c.fc2,y[9],  f2mul(c.fc3,y[10]));
    g[19] = f2fma(c.fc4,y[11], f2mul(c.fc5,y[12]));
    g[20] = f2fma(c.fe0,y[13], f2mul(c.fe1,y[14]));
    g[21] = f2fma(c.fe2,y[13], f2mul(c.fe3,y[14]));
    g[22] = f2fma(c.fe4,y[15], f2mul(c.fe5,y[16]));
    g[23] = f2fma(c.fe6,y[15], f2mul(c.fe7,y[16]));
}

__device__ __forceinline__ float softf(float g, float t)
{
    float a = fabsf(g) - t;
    float m = fmaxf(a, 0.0f);
    return copysignf(m, g);
}

__global__ __launch_bounds__(32) void pdhg_kernel(const float* __restrict__ xtraj,
                                                  const float* __restrict__ x,
                                                  float* __restrict__ out)
{
    int i = blockIdx.x*32 + threadIdx.x;
    if (i >= NPROB/2) return;
    int pA = 2*i, pB = pA + 1;
    int bA = pA/TT, tA = pA%TT;
    int bB = pB/TT, tB = pB%TT;
    const float *XA = xtraj + bA*45, *XB = xtraj + bB*45;
    const float *xA = x + bA*160,    *xB = x + bB*160;
    const float *vA = g_v + bA*40,   *vB = g_v + bB*40;
    const float *pA_ = g_pr + bA*20, *pB_ = g_pr + bB*20;

    float r0A = XA[tA], r1A = XA[5+tA];
    float r0B = XB[tB], r1B = XB[5+tB];

    CP c;
    c.M1  = mkf2(-1.f, -1.f);
    u64 nddr0 = mkf2(-XA[30+tA], -XB[30+tB]);
    u64 nddr1 = mkf2(-XA[35+tA], -XB[35+tB]);
    u64 nddr2 = mkf2(-XA[40+tA], -XB[40+tB]);
    c.fc0 = mkf2(xA[20+tA], xB[20+tB]);  c.fc1 = mkf2(xA[25+tA], xB[25+tB]);
    c.fc2 = mkf2(xA[30+tA], xB[30+tB]);  c.fc3 = mkf2(xA[35+tA], xB[35+tB]);
    c.fc4 = mkf2(xA[40+tA], xB[40+tB]);  c.fc5 = mkf2(xA[45+tA], xB[45+tB]);
    c.fe0 = mkf2(xA[80+tA],  xB[80+tB]);  c.fe1 = mkf2(xA[85+tA],  xB[85+tB]);
    c.fe2 = mkf2(xA[90+tA],  xB[90+tB]);  c.fe3 = mkf2(xA[95+tA],  xB[95+tB]);
    c.fe4 = mkf2(xA[100+tA], xB[100+tB]); c.fe5 = mkf2(xA[105+tA], xB[105+tB]);
    c.fe6 = mkf2(xA[110+tA], xB[110+tB]); c.fe7 = mkf2(xA[115+tA], xB[115+tB]);
    c.nv0 = mkf2(-vA[tA],    -vB[tB]);    c.nv1 = mkf2(-vA[5+tA],  -vB[5+tB]);
    c.nv2 = mkf2(-vA[10+tA], -vB[10+tB]); c.nv3 = mkf2(-vA[15+tA], -vB[15+tB]);
    c.nv4 = mkf2(-vA[20+tA], -vB[20+tB]); c.nv5 = mkf2(-vA[25+tA], -vB[25+tB]);
    c.a24 = mkf2(-(pA_[10+tA]-r1A), -(pB_[10+tB]-r1B));
    c.a25 = mkf2(-(pA_[15+tA]-r1A), -(pB_[15+tB]-r1B));
    c.a26 = mkf2( pA_[tA]   - r0A,   pB_[tB]   - r0B);
    c.a27 = mkf2( pA_[5+tA] - r0A,   pB_[5+tB] - r0B);
    c.a28 = mkf2(-(xA[70+tA]-r1A), -(xB[70+tB]-r1B));
    c.a29 = mkf2(-(xA[75+tA]-r1A), -(xB[75+tB]-r1B));
    c.a2a = mkf2( xA[60+tA] - r0A,   xB[60+tB] - r0B);
    c.a2b = mkf2( xA[65+tA] - r0A,   xB[65+tB] - r0B);

    // ----- spectral norm: 25 power iterations of u <- A^T A u (normalized) -----
    u64 u[24];
#pragma unroll
    for (int k = 0; k < 24; k++) u[k] = mkf2(1.f, 1.f);
    for (int it = 0; it < 25; it++) {
        u64 w[17], un[24];
        amul2(c, u, w);
        atmul2(c, w, un);
        u64 acc = mkf2(0.f, 0.f);
#pragma unroll
        for (int k = 0; k < 24; k++) acc = f2fma(un[k], un[k], acc);
        float2 sp = unf2(acc);
        float invA = 1.0f/(sqrtf(sp.x) + 1e-12f);
        float invB = 1.0f/(sqrtf(sp.y) + 1e-12f);
        u64 inv2 = mkf2(invA, invB);
#pragma unroll
        for (int k = 0; k < 24; k++) u[k] = f2mul(un[k], inv2);
    }
    float tauA, tauB;
    {
        u64 w[17];
        amul2(c, u, w);
        u64 acc = mkf2(0.f, 0.f);
#pragma unroll
        for (int e = 0; e < 17; e++) acc = f2fma(w[e], w[e], acc);
        float2 sp = unf2(acc);
        tauA = 0.9f/(sqrtf(sp.x) + 1e-8f);
        tauB = 0.9f/(sqrtf(sp.y) + 1e-8f);
    }
    u64 sig  = mkf2(tauA, tauB);
    u64 ntau = mkf2(-tauA, -tauB);

    // ----- PDHG (Chambolle-Pock), 400 iterations -----
    u64 z[24], zb[24], y[17];
    u64 ZERO = mkf2(0.f, 0.f);
#pragma unroll
    for (int k = 0; k < 24; k++) { z[k] = ZERO; zb[k] = ZERO; }
#pragma unroll
    for (int e = 0; e < 17; e++) y[e] = ZERO;

    for (int it = 0; it < 400; it++) {
        u64 az[17];
        amul2(c, zb, az);
        y[0] = f2fma(sig, f2add(az[0], nddr0), y[0]);
        y[1] = f2fma(sig, f2add(az[1], nddr1), y[1]);
        y[2] = f2fma(sig, f2add(az[2], nddr2), y[2]);
        y[3] = f2fma(sig, az[3], y[3]);
        y[4] = f2fma(sig, az[4], y[4]);
        y[5] = f2fma(sig, f2add(az[5], c.M1), y[5]);
        y[6] = f2fma(sig, az[6], y[6]);
        y[7] = f2fma(sig, az[7], y[7]);
        y[8] = f2fma(sig, f2add(az[8], c.M1), y[8]);
#pragma unroll
        for (int e = 9; e < 17; e++) y[e] = f2fma(sig, az[e], y[e]);

        u64 g[24];
        atmul2(c, y, g);
#pragma unroll
        for (int k = 0; k < 24; k++) g[k] = f2fma(ntau, g[k], z[k]);  // g = z - tau*A^T y

        // prox + overrelax + commit
#pragma unroll
        for (int k = 0; k < 4; k++) {      // free coords 0..3
            u64 zn = g[k];
            zb[k] = f2add(zn, f2fma(z[k], c.M1, zn));
            z[k] = zn;
        }
#pragma unroll
        for (int k = 4; k < 8; k++) {      // L1 coords 4..7
            float2 p = unf2(g[k]);
            u64 zn = mkf2(softf(p.x, tauA), softf(p.y, tauB));
            zb[k] = f2add(zn, f2fma(z[k], c.M1, zn));
            z[k] = zn;
        }
#pragma unroll
        for (int k = 8; k < 12; k++) {     // free coords 8..11
            u64 zn = g[k];
            zb[k] = f2add(zn, f2fma(z[k], c.M1, zn));
            z[k] = zn;
        }
#pragma unroll
        for (int k = 12; k < 24; k++) {    // nonneg coords 12..23
            float2 p = unf2(g[k]);
            u64 zn = mkf2(fmaxf(p.x, 0.f), fmaxf(p.y, 0.f));
            zb[k] = f2add(zn, f2fma(z[k], c.M1, zn));
            z[k] = zn;
        }
    }

    // ----- write p, f parts of output (scaled by 100) -----
#pragma unroll
    for (int k = 0; k < 4; k++) {
        float2 p = unf2(z[k]);
        out[bA*100 + k*5 + tA] = 100.0f * p.x;
        out[bB*100 + k*5 + tB] = 100.0f * p.y;
    }
#pragma unroll
    for (int k = 0; k < 4; k++) {
        float2 p = unf2(z[4+k]);
        out[bA*100 + 20 + k*5 + tA] = 100.0f * p.x;
        out[bB*100 + 20 + k*5 + tB] = 100.0f * p.y;
    }
}

// ---------------- tail: out[:,40:100] = 1000*(p_r - x[:,0:20]), 1000*(v - x[:,120:160]) ----
__global__ void tail_kernel(const float* __restrict__ x, float* __restrict__ out)
{
    int idx = blockIdx.x*blockDim.x + threadIdx.x;
    if (idx >= BATCH*60) return;
    int b = idx/60, j = idx%60;
    if (j < 20) out[b*100 + 40 + j] = 1000.0f*(g_pr[b*20 + j] - x[b*160 + j]);
    else {
        int k = j - 20;
        out[b*100 + 60 + k] = 1000.0f*(g_v[b*40 + k] - x[b*160 + 120 + k]);
    }
}

// ---------------- launch ----------------
extern "C" void kernel_launch(void* const* d_in, const int* in_sizes, int n_in,
                              void* d_out, int out_size)
{
    const float* xtraj = (const float*)d_in[0];
    const float* x     = (const float*)d_in[1];
    const float* x_img = (const float*)d_in[2];
    const float* cw1   = (const float*)d_in[3];
    const float* cb1   = (const float*)d_in[4];
    const float* cw2   = (const float*)d_in[5];
    const float* cb2   = (const float*)d_in[6];
    const float* w3    = (const float*)d_in[7];
    const float* b3    = (const float*)d_in[8];
    const float* w4    = (const float*)d_in[9];
    const float* b4    = (const float*)d_in[10];
    const float* pw1   = (const float*)d_in[11];
    const float* pb1   = (const float*)d_in[12];
    const float* pw2   = (const float*)d_in[13];
    const float* pb2   = (const float*)d_in[14];
    const float* pw3   = (const float*)d_in[15];
    const float* pb3   = (const float*)d_in[16];
    const float* vw1   = (const float*)d_in[17];
    const float* vb1   = (const float*)d_in[18];
    const float* vw2   = (const float*)d_in[19];
    const float* vb2   = (const float*)d_in[20];
    const float* vw3   = (const float*)d_in[21];
    const float* vb3   = (const float*)d_in[22];
    float* out = (float*)d_out;

    transpose_w<<<(118000 + 255)/256, 256>>>(w3, w4, pw1, vw1, pw2, vw2, pw3, vw3);
    conv1_kernel<<<BATCH, 400>>>(x_img, cw1, cb1);
    conv2_kernel<<<BATCH, 320>>>(cw2, cb2);
    mlp_kernel<<<BATCH/4, 128>>>(xtraj, b3, b4, pb1, vb1, pb2, vb2, pb3, vb3);
    pdhg_kernel<<<(NPROB/2 + 31)/32, 32>>>(xtraj, x, out);
    tail_kernel<<<(BATCH*60 + 255)/256, 256>>>(x, out);
}

// round 8
// speedup vs baseline: 1.4303x; 1.4303x over previous
#include <cuda_runtime.h>
#include <math.h>

#define BATCH 512
#define TT 5
#define NPROB (BATCH*TT)

// ---------------- scratch (device globals: no allocation allowed) ----------------
__device__ float g_h1[BATCH*10*20*20];   // conv1+pool output
__device__ float g_h2[BATCH*320];        // conv2+pool output (flattened)
__device__ float g_t150[BATCH*150];
__device__ float g_h145[BATCH*145];
__device__ float g_ta[BATCH*100];
__device__ float g_tb[BATCH*100];
__device__ float g_pr[BATCH*20];
__device__ float g_v[BATCH*40];

// ================= packed f32x2 helpers =================
typedef unsigned long long u64;
__device__ __forceinline__ u64 mkf2(float lo, float hi){ u64 r; asm("mov.b64 %0,{%1,%2};":"=l"(r):"f"(lo),"f"(hi)); return r; }
__device__ __forceinline__ float2 unf2(u64 v){ float2 p; asm("mov.b64 {%0,%1},%2;":"=f"(p.x),"=f"(p.y):"l"(v)); return p; }
__device__ __forceinline__ u64 f2fma(u64 a,u64 b,u64 c){ u64 d; asm("fma.rn.f32x2 %0,%1,%2,%3;":"=l"(d):"l"(a),"l"(b),"l"(c)); return d; }
__device__ __forceinline__ u64 f2add(u64 a,u64 b){ u64 d; asm("add.rn.f32x2 %0,%1,%2;":"=l"(d):"l"(a),"l"(b)); return d; }
__device__ __forceinline__ u64 f2mul(u64 a,u64 b){ u64 d; asm("mul.rn.f32x2 %0,%1,%2;":"=l"(d):"l"(a),"l"(b)); return d; }

// ---------------- conv1: (B,1,50,50) -> conv 11x11 -> pool2 -> relu -> (B,10,20,20) ----
__global__ void conv1_kernel(const float* __restrict__ img,
                             const float* __restrict__ w,
                             const float* __restrict__ bias)
{
    __shared__ float sIm[2500];
    __shared__ float sW[1210];
    __shared__ float sB[10];
    int b = blockIdx.x;
    int tid = threadIdx.x;  // 0..399
    for (int i = tid; i < 2500; i += 400) sIm[i] = img[b*2500 + i];
    for (int i = tid; i < 1210; i += 400) sW[i] = w[i];
    if (tid < 10) sB[tid] = bias[tid];
    __syncthreads();

    int oy = tid / 20, ox = tid % 20;
    float acc[10][4];
#pragma unroll
    for (int c = 0; c < 10; c++) { acc[c][0]=0.f; acc[c][1]=0.f; acc[c][2]=0.f; acc[c][3]=0.f; }
    int iy0 = 2*oy, ix0 = 2*ox;
    for (int ky = 0; ky < 11; ky++) {
        const float* row0 = &sIm[(iy0+ky)*50 + ix0];
        const float* row1 = row0 + 50;
#pragma unroll
        for (int kx = 0; kx < 11; kx++) {
            float p00 = row0[kx], p01 = row0[kx+1];
            float p10 = row1[kx], p11 = row1[kx+1];
#pragma unroll
            for (int c = 0; c < 10; c++) {
                float wv = sW[c*121 + ky*11 + kx];
                acc[c][0] += wv*p00; acc[c][1] += wv*p01;
                acc[c][2] += wv*p10; acc[c][3] += wv*p11;
            }
        }
    }
#pragma unroll
    for (int c = 0; c < 10; c++) {
        float m = fmaxf(fmaxf(acc[c][0],acc[c][1]), fmaxf(acc[c][2],acc[c][3]));
        m += sB[c];
        g_h1[((b*10 + c)*20 + oy)*20 + ox] = fmaxf(m, 0.0f);
    }
}

// ---------------- conv2: (B,10,20,20) -> conv 5x5 (20 out) -> pool4 -> relu -> (B,320) ----
__global__ void conv2_kernel(const float* __restrict__ w,   // (20,10,5,5)
                             const float* __restrict__ bias)
{
    __shared__ __align__(16) float sm[9024];
    float* sIn = sm;          // 4000
    float* sW  = sm + 4000;   // 5000 rearranged: [ci][ky][kx][c], c contiguous (20)
    int b = blockIdx.x;
    int tid = threadIdx.x;    // 0..319
    for (int i = tid; i < 4000; i += 320) sIn[i] = g_h1[b*4000 + i];
    for (int i = tid; i < 5000; i += 320) {
        int c = i % 20;
        int r = i / 20;       // ci*25 + ky*5 + kx
        sW[i] = w[c*250 + r];
    }
    __syncthreads();

    bool active = tid < 256;
    int ix = tid & 3, iy = (tid>>2)&3, px = (tid>>4)&3, py = (tid>>6)&3;
    int Y = py*4 + iy, X = px*4 + ix;
    float acc[20];
#pragma unroll
    for (int c = 0; c < 20; c++) acc[c] = 0.0f;
    if (active) {
        for (int ci = 0; ci < 10; ci++) {
            const float* inp = &sIn[ci*400 + Y*20 + X];
#pragma unroll
            for (int ky = 0; ky < 5; ky++) {
#pragma unroll
                for (int kx = 0; kx < 5; kx++) {
                    float pix = inp[ky*20 + kx];
                    const float4* wp = (const float4*)&sW[(ci*25 + ky*5 + kx)*20];
#pragma unroll
                    for (int j = 0; j < 5; j++) {
                        float4 wv = wp[j];
                        acc[4*j+0] += wv.x*pix;
                        acc[4*j+1] += wv.y*pix;
                        acc[4*j+2] += wv.z*pix;
                        acc[4*j+3] += wv.w*pix;
                    }
                }
            }
        }
    }
    __syncthreads();
    float* sConv = sm;
    if (active) {
        int q = py*4 + px;
        int pos = iy*4 + ix;
#pragma unroll
        for (int c = 0; c < 20; c++) sConv[(c*16 + q)*16 + pos] = acc[c];
    }
    __syncthreads();
    {
        int c = tid / 16, qq = tid % 16;
        const float* p = &sConv[(c*16+qq)*16];
        float m = p[0];
#pragma unroll
        for (int k = 1; k < 16; k++) m = fmaxf(m, p[k]);
        m += bias[c];
        g_h2[b*320 + c*16 + qq] = fmaxf(m, 0.0f);
    }
}

// ---------------- generic small GEMM: Y(M,N) = act(X(M,K) @ W(N,K)^T + b) --------------
__global__ void gemm_kernel(const float* __restrict__ X, int ldx,
                            const float* __restrict__ W,
                            const float* __restrict__ bias,
                            float* __restrict__ Y, int ldy,
                            int M, int N, int K, int relu)
{
    __shared__ float sX[16][17];
    __shared__ float sW[16][17];
    int tx = threadIdx.x, ty = threadIdx.y;
    int m = blockIdx.x*16 + ty;
    int n = blockIdx.y*16 + tx;
    float acc = 0.0f;
    for (int k0 = 0; k0 < K; k0 += 16) {
        int kx = k0 + tx;
        sX[ty][tx] = (m < M && kx < K) ? X[m*ldx + kx] : 0.0f;
        int nw = blockIdx.y*16 + tx;
        int kw = k0 + ty;
        sW[ty][tx] = (nw < N && kw < K) ? W[nw*K + kw] : 0.0f;
        __syncthreads();
#pragma unroll
        for (int kk = 0; kk < 16; kk++) acc += sX[ty][kk]*sW[kk][tx];
        __syncthreads();
    }
    if (m < M && n < N) {
        float r = acc + bias[n];
        if (relu) r = fmaxf(r, 0.0f);
        Y[m*ldy + n] = r;
    }
}

// ---------------- concat xtraj into h145[:,100:145] ----------------
__global__ void concat_kernel(const float* __restrict__ xtraj)
{
    int idx = blockIdx.x*blockDim.x + threadIdx.x;
    if (idx < BATCH*45) {
        int b = idx/45, j = idx%45;
        g_h145[b*145 + 100 + j] = xtraj[idx];
    }
}

// ---------------- PDHG solver: packed f32x2, two problems per thread -------------
struct CP {
    u64 a24,a25,a26,a27,a28,a29,a2a,a2b;
    u64 nv0,nv1,nv2,nv3,nv4,nv5;
    u64 fc0,fc1,fc2,fc3,fc4,fc5;
    u64 fe0,fe1,fe2,fe3,fe4,fe5,fe6,fe7;
    u64 M1;
};

__device__ __forceinline__ void amul2(const CP& c, const u64* s, u64* az)
{
    az[0]  = f2add(f2add(f2add(s[4],s[5]), f2add(s[6],s[7])), f2add(s[8],s[9]));
    az[1]  = f2add(s[10],s[11]);
    az[2]  = f2fma(c.a26,s[6], f2fma(c.a24,s[4], f2fma(c.a27,s[7], f2fma(c.a25,s[5],
             f2fma(c.a2a,s[10], f2fma(c.a28,s[8], f2fma(c.a2b,s[11], f2mul(c.a29,s[9]))))))));
    az[3]  = f2fma(c.nv0,s[12], f2fma(c.nv2,s[14], s[0]));
    az[4]  = f2fma(c.nv1,s[12], f2fma(c.nv3,s[14], s[2]));
    az[5]  = f2add(s[12],s[14]);
    az[6]  = f2fma(c.nv2,s[13], f2fma(c.nv4,s[15], s[1]));
    az[7]  = f2fma(c.nv3,s[13], f2fma(c.nv5,s[15], s[3]));
    az[8]  = f2add(s[13],s[15]);
    az[9]  = f2fma(c.fc0,s[16], f2fma(c.fc2,s[18], f2mul(s[4],c.M1)));
    az[10] = f2fma(c.fc1,s[16], f2fma(c.fc3,s[18], f2mul(s[6],c.M1)));
    az[11] = f2fma(c.fc2,s[17], f2fma(c.fc4,s[19], f2mul(s[5],c.M1)));
    az[12] = f2fma(c.fc3,s[17], f2fma(c.fc5,s[19], f2mul(s[7],c.M1)));
    az[13] = f2fma(c.fe0,s[20], f2fma(c.fe2,s[21], f2mul(s[8],c.M1)));
    az[14] = f2fma(c.fe1,s[20], f2fma(c.fe3,s[21], f2mul(s[10],c.M1)));
    az[15] = f2fma(c.fe4,s[22], f2fma(c.fe6,s[23], f2mul(s[9],c.M1)));
    az[16] = f2fma(c.fe5,s[22], f2fma(c.fe7,s[23], f2mul(s[11],c.M1)));
}

__device__ __forceinline__ void atmul2(const CP& c, const u64* y, u64* g)
{
    g[0]  = y[3]; g[1] = y[6]; g[2] = y[4]; g[3] = y[7];
    g[4]  = f2fma(c.a24,y[2], f2fma(y[9], c.M1, y[0]));
    g[5]  = f2fma(c.a25,y[2], f2fma(y[11],c.M1, y[0]));
    g[6]  = f2fma(c.a26,y[2], f2fma(y[10],c.M1, y[0]));
    g[7]  = f2fma(c.a27,y[2], f2fma(y[12],c.M1, y[0]));
    g[8]  = f2fma(c.a28,y[2], f2fma(y[13],c.M1, y[0]));
    g[9]  = f2fma(c.a29,y[2], f2fma(y[15],c.M1, y[0]));
    g[10] = f2fma(c.a2a,y[2], f2fma(y[14],c.M1, y[1]));
    g[11] = f2fma(c.a2b,y[2], f2fma(y[16],c.M1, y[1]));
    g[12] = f2fma(c.nv0,y[3], f2fma(c.nv1,y[4], y[5]));
    g[13] = f2fma(c.nv2,y[6], f2fma(c.nv3,y[7], y[8]));
    g[14] = f2fma(c.nv2,y[3], f2fma(c.nv3,y[4], y[5]));
    g[15] = f2fma(c.nv4,y[6], f2fma(c.nv5,y[7], y[8]));
    g[16] = f2fma(c.fc0,y[9],  f2mul(c.fc1,y[10]));
    g[17] = f2fma(c.fc2,y[11], f2mul(c.fc3,y[12]));
    g[18] = f2fma(c.fc2,y[9],  f2mul(c.fc3,y[10]));
    g[19] = f2fma(c.fc4,y[11], f2mul(c.fc5,y[12]));
    g[20] = f2fma(c.fe0,y[13], f2mul(c.fe1,y[14]));
    g[21] = f2fma(c.fe2,y[13], f2mul(c.fe3,y[14]));
    g[22] = f2fma(c.fe4,y[15], f2mul(c.fe5,y[16]));
    g[23] = f2fma(c.fe6,y[15], f2mul(c.fe7,y[16]));
}

__device__ __forceinline__ float softf(float g, float t)
{
    float a = fabsf(g) - t;
    float m = fmaxf(a, 0.0f);
    return copysignf(m, g);
}

__global__ __launch_bounds__(32) void pdhg_kernel(const float* __restrict__ xtraj,
                                                  const float* __restrict__ x,
                                                  float* __restrict__ out)
{
    int i = blockIdx.x*32 + threadIdx.x;
    if (i >= NPROB/2) return;
    int pA = 2*i, pB = pA + 1;
    int bA = pA/TT, tA = pA%TT;
    int bB = pB/TT, tB = pB%TT;
    const float *XA = xtraj + bA*45, *XB = xtraj + bB*45;
    const float *xA = x + bA*160,    *xB = x + bB*160;
    const float *vA = g_v + bA*40,   *vB = g_v + bB*40;
    const float *pA_ = g_pr + bA*20, *pB_ = g_pr + bB*20;

    float r0A = XA[tA], r1A = XA[5+tA];
    float r0B = XB[tB], r1B = XB[5+tB];

    CP c;
    c.M1  = mkf2(-1.f, -1.f);
    u64 nddr0 = mkf2(-XA[30+tA], -XB[30+tB]);
    u64 nddr1 = mkf2(-XA[35+tA], -XB[35+tB]);
    u64 nddr2 = mkf2(-XA[40+tA], -XB[40+tB]);
    c.fc0 = mkf2(xA[20+tA], xB[20+tB]);  c.fc1 = mkf2(xA[25+tA], xB[25+tB]);
    c.fc2 = mkf2(xA[30+tA], xB[30+tB]);  c.fc3 = mkf2(xA[35+tA], xB[35+tB]);
    c.fc4 = mkf2(xA[40+tA], xB[40+tB]);  c.fc5 = mkf2(xA[45+tA], xB[45+tB]);
    c.fe0 = mkf2(xA[80+tA],  xB[80+tB]);  c.fe1 = mkf2(xA[85+tA],  xB[85+tB]);
    c.fe2 = mkf2(xA[90+tA],  xB[90+tB]);  c.fe3 = mkf2(xA[95+tA],  xB[95+tB]);
    c.fe4 = mkf2(xA[100+tA], xB[100+tB]); c.fe5 = mkf2(xA[105+tA], xB[105+tB]);
    c.fe6 = mkf2(xA[110+tA], xB[110+tB]); c.fe7 = mkf2(xA[115+tA], xB[115+tB]);
    c.nv0 = mkf2(-vA[tA],    -vB[tB]);    c.nv1 = mkf2(-vA[5+tA],  -vB[5+tB]);
    c.nv2 = mkf2(-vA[10+tA], -vB[10+tB]); c.nv3 = mkf2(-vA[15+tA], -vB[15+tB]);
    c.nv4 = mkf2(-vA[20+tA], -vB[20+tB]); c.nv5 = mkf2(-vA[25+tA], -vB[25+tB]);
    c.a24 = mkf2(-(pA_[10+tA]-r1A), -(pB_[10+tB]-r1B));
    c.a25 = mkf2(-(pA_[15+tA]-r1A), -(pB_[15+tB]-r1B));
    c.a26 = mkf2( pA_[tA]   - r0A,   pB_[tB]   - r0B);
    c.a27 = mkf2( pA_[5+tA] - r0A,   pB_[5+tB] - r0B);
    c.a28 = mkf2(-(xA[70+tA]-r1A), -(xB[70+tB]-r1B));
    c.a29 = mkf2(-(xA[75+tA]-r1A), -(xB[75+tB]-r1B));
    c.a2a = mkf2( xA[60+tA] - r0A,   xB[60+tB] - r0B);
    c.a2b = mkf2( xA[65+tA] - r0A,   xB[65+tB] - r0B);

    // ----- spectral norm: 25 power iterations of u <- A^T A u (normalized) -----
    u64 u[24];
#pragma unroll
    for (int k = 0; k < 24; k++) u[k] = mkf2(1.f, 1.f);
    for (int it = 0; it < 25; it++) {
        u64 w[17], un[24];
        amul2(c, u, w);
        atmul2(c, w, un);
        u64 acc = mkf2(0.f, 0.f);
#pragma unroll
        for (int k = 0; k < 24; k++) acc = f2fma(un[k], un[k], acc);
        float2 sp = unf2(acc);
        float invA = 1.0f/(sqrtf(sp.x) + 1e-12f);
        float invB = 1.0f/(sqrtf(sp.y) + 1e-12f);
        u64 inv2 = mkf2(invA, invB);
#pragma unroll
        for (int k = 0; k < 24; k++) u[k] = f2mul(un[k], inv2);
    }
    float tauA, tauB;
    {
        u64 w[17];
        amul2(c, u, w);
        u64 acc = mkf2(0.f, 0.f);
#pragma unroll
        for (int e = 0; e < 17; e++) acc = f2fma(w[e], w[e], acc);
        float2 sp = unf2(acc);
        tauA = 0.9f/(sqrtf(sp.x) + 1e-8f);
        tauB = 0.9f/(sqrtf(sp.y) + 1e-8f);
    }
    u64 sig  = mkf2(tauA, tauB);
    u64 ntau = mkf2(-tauA, -tauB);

    // ----- PDHG (Chambolle-Pock), 400 iterations -----
    u64 z[24], zb[24], y[17];
    u64 ZERO = mkf2(0.f, 0.f);
#pragma unroll
    for (int k = 0; k < 24; k++) { z[k] = ZERO; zb[k] = ZERO; }
#pragma unroll
    for (int e = 0; e < 17; e++) y[e] = ZERO;

    for (int it = 0; it < 400; it++) {
        u64 az[17];
        amul2(c, zb, az);
        y[0] = f2fma(sig, f2add(az[0], nddr0), y[0]);
        y[1] = f2fma(sig, f2add(az[1], nddr1), y[1]);
        y[2] = f2fma(sig, f2add(az[2], nddr2), y[2]);
        y[3] = f2fma(sig, az[3], y[3]);
        y[4] = f2fma(sig, az[4], y[4]);
        y[5] = f2fma(sig, f2add(az[5], c.M1), y[5]);
        y[6] = f2fma(sig, az[6], y[6]);
        y[7] = f2fma(sig, az[7], y[7]);
        y[8] = f2fma(sig, f2add(az[8], c.M1), y[8]);
#pragma unroll
        for (int e = 9; e < 17; e++) y[e] = f2fma(sig, az[e], y[e]);

        u64 g[24];
        atmul2(c, y, g);
#pragma unroll
        for (int k = 0; k < 24; k++) g[k] = f2fma(ntau, g[k], z[k]);  // g = z - tau*A^T y

        // prox + overrelax + commit
#pragma unroll
        for (int k = 0; k < 4; k++) {      // free coords 0..3
            u64 zn = g[k];
            zb[k] = f2add(zn, f2fma(z[k], c.M1, zn));
            z[k] = zn;
        }
#pragma unroll
        for (int k = 4; k < 8; k++) {      // L1 coords 4..7
            float2 p = unf2(g[k]);
            u64 zn = mkf2(softf(p.x, tauA), softf(p.y, tauB));
            zb[k] = f2add(zn, f2fma(z[k], c.M1, zn));
            z[k] = zn;
        }
#pragma unroll
        for (int k = 8; k < 12; k++) {     // free coords 8..11
            u64 zn = g[k];
            zb[k] = f2add(zn, f2fma(z[k], c.M1, zn));
            z[k] = zn;
        }
#pragma unroll
        for (int k = 12; k < 24; k++) {    // nonneg coords 12..23
            float2 p = unf2(g[k]);
            u64 zn = mkf2(fmaxf(p.x, 0.f), fmaxf(p.y, 0.f));
            zb[k] = f2add(zn, f2fma(z[k], c.M1, zn));
            z[k] = zn;
        }
    }

    // ----- write p, f parts of output (scaled by 100) -----
#pragma unroll
    for (int k = 0; k < 4; k++) {
        float2 p = unf2(z[k]);
        out[bA*100 + k*5 + tA] = 100.0f * p.x;
        out[bB*100 + k*5 + tB] = 100.0f * p.y;
    }
#pragma unroll
    for (int k = 0; k < 4; k++) {
        float2 p = unf2(z[4+k]);
        out[bA*100 + 20 + k*5 + tA] = 100.0f * p.x;
        out[bB*100 + 20 + k*5 + tB] = 100.0f * p.y;
    }
}

// ---------------- tail: out[:,40:100] = 1000*(p_r - x[:,0:20]), 1000*(v - x[:,120:160]) ----
__global__ void tail_kernel(const float* __restrict__ x, float* __restrict__ out)
{
    int idx = blockIdx.x*blockDim.x + threadIdx.x;
    if (idx >= BATCH*60) return;
    int b = idx/60, j = idx%60;
    if (j < 20) out[b*100 + 40 + j] = 1000.0f*(g_pr[b*20 + j] - x[b*160 + j]);
    else {
        int k = j - 20;
        out[b*100 + 60 + k] = 1000.0f*(g_v[b*40 + k] - x[b*160 + 120 + k]);
    }
}

// ---------------- launch ----------------
extern "C" void kernel_launch(void* const* d_in, const int* in_sizes, int n_in,
                              void* d_out, int out_size)
{
    const float* xtraj = (const float*)d_in[0];
    const float* x     = (const float*)d_in[1];
    const float* x_img = (const float*)d_in[2];
    const float* cw1   = (const float*)d_in[3];
    const float* cb1   = (const float*)d_in[4];
    const float* cw2   = (const float*)d_in[5];
    const float* cb2   = (const float*)d_in[6];
    const float* w3    = (const float*)d_in[7];
    const float* b3    = (const float*)d_in[8];
    const float* w4    = (const float*)d_in[9];
    const float* b4    = (const float*)d_in[10];
    const float* pw1   = (const float*)d_in[11];
    const float* pb1   = (const float*)d_in[12];
    const float* pw2   = (const float*)d_in[13];
    const float* pb2   = (const float*)d_in[14];
    const float* pw3   = (const float*)d_in[15];
    const float* pb3   = (const float*)d_in[16];
    const float* vw1   = (const float*)d_in[17];
    const float* vb1   = (const float*)d_in[18];
    const float* vw2   = (const float*)d_in[19];
    const float* vb2   = (const float*)d_in[20];
    const float* vw3   = (const float*)d_in[21];
    const float* vb3   = (const float*)d_in[22];
    float* out = (float*)d_out;

    float *p_h2, *p_t150, *p_h145, *p_ta, *p_tb, *p_pr, *p_v;
    cudaGetSymbolAddress((void**)&p_h2,   g_h2);
    cudaGetSymbolAddress((void**)&p_t150, g_t150);
    cudaGetSymbolAddress((void**)&p_h145, g_h145);
    cudaGetSymbolAddress((void**)&p_ta,   g_ta);
    cudaGetSymbolAddress((void**)&p_tb,   g_tb);
    cudaGetSymbolAddress((void**)&p_pr,   g_pr);
    cudaGetSymbolAddress((void**)&p_v,    g_v);

    dim3 tb16(16,16);

    conv1_kernel<<<BATCH, 400>>>(x_img, cw1, cb1);
    conv2_kernel<<<BATCH, 320>>>(cw2, cb2);

    // encoder FCs
    gemm_kernel<<<dim3(32, 10), tb16>>>(p_h2, 320, w3, b3, p_t150, 150, BATCH, 150, 320, 1);
    gemm_kernel<<<dim3(32, 7),  tb16>>>(p_t150, 150, w4, b4, p_h145, 145, BATCH, 100, 150, 1);
    concat_kernel<<<(BATCH*45 + 255)/256, 256>>>(xtraj);

    // p head
    gemm_kernel<<<dim3(32, 7), tb16>>>(p_h145, 145, pw1, pb1, p_ta, 100, BATCH, 100, 145, 1);
    gemm_kernel<<<dim3(32, 7), tb16>>>(p_ta, 100, pw2, pb2, p_tb, 100, BATCH, 100, 100, 1);
    gemm_kernel<<<dim3(32, 2), tb16>>>(p_tb, 100, pw3, pb3, p_pr, 20, BATCH, 20, 100, 0);

    // v head
    gemm_kernel<<<dim3(32, 7), tb16>>>(p_h145, 145, vw1, vb1, p_ta, 100, BATCH, 100, 145, 1);
    gemm_kernel<<<dim3(32, 7), tb16>>>(p_ta, 100, vw2, vb2, p_tb, 100, BATCH, 100, 100, 1);
    gemm_kernel<<<dim3(32, 3), tb16>>>(p_tb, 100, vw3, vb3, p_v, 40, BATCH, 40, 100, 0);

    // LP solves + output assembly
    pdhg_kernel<<<(NPROB/2 + 31)/32, 32>>>(xtraj, x, out);
    tail_kernel<<<(BATCH*60 + 255)/256, 256>>>(x, out);
}

// round 9
// speedup vs baseline: 1.8748x; 1.3108x over previous
#include <cuda_runtime.h>
#include <math.h>

#define BATCH 512
#define TT 5
#define NPROB (BATCH*TT)

// ---------------- scratch (device globals: no allocation allowed) ----------------
__device__ float g_h1[BATCH*10*20*20];   // conv1+pool output
__device__ float g_h2[BATCH*320];        // conv2+pool output (flattened)
__device__ float g_pr[BATCH*20];
__device__ float g_v[BATCH*40];
__device__ __align__(16) float g_wT[118000];  // transposed weights

// ---------------- conv1: (B,1,50,50) -> conv 11x11 -> pool2 -> relu -> (B,10,20,20) ----
__global__ void conv1_kernel(const float* __restrict__ img,
                             const float* __restrict__ w,
                             const float* __restrict__ bias)
{
    __shared__ float sIm[2500];
    __shared__ float sW[1210];
    __shared__ float sB[10];
    int b = blockIdx.x;
    int tid = threadIdx.x;  // 0..399
    for (int i = tid; i < 2500; i += 400) sIm[i] = img[b*2500 + i];
    for (int i = tid; i < 1210; i += 400) sW[i] = w[i];
    if (tid < 10) sB[tid] = bias[tid];
    __syncthreads();

    int oy = tid / 20, ox = tid % 20;
    float acc[10][4];
#pragma unroll
    for (int c = 0; c < 10; c++) { acc[c][0]=0.f; acc[c][1]=0.f; acc[c][2]=0.f; acc[c][3]=0.f; }
    int iy0 = 2*oy, ix0 = 2*ox;
    for (int ky = 0; ky < 11; ky++) {
        const float* row0 = &sIm[(iy0+ky)*50 + ix0];
        const float* row1 = row0 + 50;
#pragma unroll
        for (int kx = 0; kx < 11; kx++) {
            float p00 = row0[kx], p01 = row0[kx+1];
            float p10 = row1[kx], p11 = row1[kx+1];
#pragma unroll
            for (int c = 0; c < 10; c++) {
                float wv = sW[c*121 + ky*11 + kx];
                acc[c][0] += wv*p00; acc[c][1] += wv*p01;
                acc[c][2] += wv*p10; acc[c][3] += wv*p11;
            }
        }
    }
#pragma unroll
    for (int c = 0; c < 10; c++) {
        float m = fmaxf(fmaxf(acc[c][0],acc[c][1]), fmaxf(acc[c][2],acc[c][3]));
        m += sB[c];
        g_h1[((b*10 + c)*20 + oy)*20 + ox] = fmaxf(m, 0.0f);
    }
}

// ---------------- conv2: (B,10,20,20) -> conv 5x5 (20 out) -> pool4 -> relu -> (B,320) ----
__global__ void conv2_kernel(const float* __restrict__ w,   // (20,10,5,5)
                             const float* __restrict__ bias)
{
    __shared__ __align__(16) float sm[9024];
    float* sIn = sm;          // 4000
    float* sW  = sm + 4000;   // 5000 rearranged: [ci][ky][kx][c], c contiguous (20)
    int b = blockIdx.x;
    int tid = threadIdx.x;    // 0..319
    for (int i = tid; i < 4000; i += 320) sIn[i] = g_h1[b*4000 + i];
    for (int i = tid; i < 5000; i += 320) {
        int c = i % 20;
        int r = i / 20;       // ci*25 + ky*5 + kx
        sW[i] = w[c*250 + r];
    }
    __syncthreads();

    bool active = tid < 256;
    int ix = tid & 3, iy = (tid>>2)&3, px = (tid>>4)&3, py = (tid>>6)&3;
    int Y = py*4 + iy, X = px*4 + ix;
    float acc[20];
#pragma unroll
    for (int c = 0; c < 20; c++) acc[c] = 0.0f;
    if (active) {
        for (int ci = 0; ci < 10; ci++) {
            const float* inp = &sIn[ci*400 + Y*20 + X];
#pragma unroll
            for (int ky = 0; ky < 5; ky++) {
#pragma unroll
                for (int kx = 0; kx < 5; kx++) {
                    float pix = inp[ky*20 + kx];
                    const float4* wp = (const float4*)&sW[(ci*25 + ky*5 + kx)*20];
#pragma unroll
                    for (int j = 0; j < 5; j++) {
                        float4 wv = wp[j];
                        acc[4*j+0] += wv.x*pix;
                        acc[4*j+1] += wv.y*pix;
                        acc[4*j+2] += wv.z*pix;
                        acc[4*j+3] += wv.w*pix;
                    }
                }
            }
        }
    }
    __syncthreads();
    float* sConv = sm;
    if (active) {
        int q = py*4 + px;
        int pos = iy*4 + ix;
#pragma unroll
        for (int c = 0; c < 20; c++) sConv[(c*16 + q)*16 + pos] = acc[c];
    }
    __syncthreads();
    {
        int c = tid / 16, qq = tid % 16;
        const float* p = &sConv[(c*16+qq)*16];
        float m = p[0];
#pragma unroll
        for (int k = 1; k < 16; k++) m = fmaxf(m, p[k]);
        m += bias[c];
        g_h2[b*320 + c*16 + qq] = fmaxf(m, 0.0f);
    }
}

// ---------------- weight transpose: [N][K] -> [K][N] segments into g_wT --------------
// offsets: w3T 0(48000,[k*150+n]) w4T 48000([k*100+n]) pw1T 63000 vw1T 77500
//          pw2T 92000 vw2T 102000 pw3T 112000([k*20+n]) vw3T 114000([k*40+n])
__global__ void transpose_w(const float* __restrict__ w3, const float* __restrict__ w4,
                            const float* __restrict__ pw1, const float* __restrict__ vw1,
                            const float* __restrict__ pw2, const float* __restrict__ vw2,
                            const float* __restrict__ pw3, const float* __restrict__ vw3)
{
    int i = blockIdx.x*blockDim.x + threadIdx.x;
    if (i >= 118000) return;
    float v;
    if (i < 48000)       { int n=i%150, k=i/150;                 v = w3[n*320+k]; }
    else if (i < 63000)  { int j=i-48000;  int n=j%100, k=j/100; v = w4[n*150+k]; }
    else if (i < 77500)  { int j=i-63000;  int n=j%100, k=j/100; v = pw1[n*145+k]; }
    else if (i < 92000)  { int j=i-77500;  int n=j%100, k=j/100; v = vw1[n*145+k]; }
    else if (i < 102000) { int j=i-92000;  int n=j%100, k=j/100; v = pw2[n*100+k]; }
    else if (i < 112000) { int j=i-102000; int n=j%100, k=j/100; v = vw2[n*100+k]; }
    else if (i < 114000) { int j=i-112000; int n=j%20,  k=j/20;  v = pw3[n*100+k]; }
    else                 { int j=i-114000; int n=j%40,  k=j/40;  v = vw3[n*100+k]; }
    g_wT[i] = v;
}

// ---------------- block-parallel fused MLP: one block per sample ----------------
// Thread n computes output neuron n of each layer; X broadcast from smem,
// transposed weights give coalesced LDG across n (L1/L2-resident, shared by all blocks).
__global__ __launch_bounds__(256) void mlp_kernel(const float* __restrict__ xtraj,
    const float* __restrict__ b3, const float* __restrict__ b4,
    const float* __restrict__ pb1, const float* __restrict__ vb1,
    const float* __restrict__ pb2, const float* __restrict__ vb2,
    const float* __restrict__ pb3, const float* __restrict__ vb3)
{
    __shared__ float sA[324];
    __shared__ float sB[204];
    int b = blockIdx.x;
    int tid = threadIdx.x;

    // load h2 (320)
    if (tid < 320) sA[tid] = g_h2[b*320 + tid];
    if (tid + 256 < 320) sA[tid+256] = g_h2[b*320 + tid + 256];
    __syncthreads();

    // L1: 320 -> 150 relu
    if (tid < 150) {
        const float* W = g_wT + tid;     // [k*150 + n]
        float acc = 0.f;
#pragma unroll 8
        for (int k = 0; k < 320; k++) acc = fmaf(sA[k], W[k*150], acc);
        sB[tid] = fmaxf(acc + b3[tid], 0.f);
    }
    __syncthreads();

    // L2: 150 -> 100 relu, plus xtraj concat into sA[100:145]
    float l2 = 0.f;
    if (tid < 100) {
        const float* W = g_wT + 48000 + tid;
        float acc = 0.f;
#pragma unroll 8
        for (int k = 0; k < 150; k++) acc = fmaf(sB[k], W[k*100], acc);
        l2 = fmaxf(acc + b4[tid], 0.f);
    }
    __syncthreads();   // sB reads complete before sA overwrite below? sA write only; sB untouched
    if (tid < 100) sA[tid] = l2;
    if (tid >= 100 && tid < 145) sA[tid] = xtraj[b*45 + tid - 100];
    __syncthreads();

    // L3 dual: 145 -> 100 (p) and 145 -> 100 (v), relu
    if (tid < 200) {
        int half = tid >= 100;
        int n = half ? tid - 100 : tid;
        const float* W = g_wT + (half ? 77500 : 63000) + n;
        const float* bb = half ? vb1 : pb1;
        float acc = 0.f;
#pragma unroll 8
        for (int k = 0; k < 145; k++) acc = fmaf(sA[k], W[k*100], acc);
        sB[tid] = fmaxf(acc + bb[n], 0.f);
    }
    __syncthreads();

    // L4 dual: 100 -> 100 each head, relu
    float l4 = 0.f;
    if (tid < 200) {
        int half = tid >= 100;
        int n = half ? tid - 100 : tid;
        const float* X = half ? sB + 100 : sB;
        const float* W = g_wT + (half ? 102000 : 92000) + n;
        const float* bb = half ? vb2 : pb2;
        float acc = 0.f;
#pragma unroll 8
        for (int k = 0; k < 100; k++) acc = fmaf(X[k], W[k*100], acc);
        l4 = fmaxf(acc + bb[n], 0.f);
    }
    __syncthreads();
    if (tid < 200) sA[tid] = l4;
    __syncthreads();

    // L5 dual: 100 -> 20 (p_r) and 100 -> 40 (v), linear, straight to global
    if (tid < 20) {
        const float* W = g_wT + 112000 + tid;
        float acc = 0.f;
#pragma unroll 8
        for (int k = 0; k < 100; k++) acc = fmaf(sA[k], W[k*20], acc);
        g_pr[b*20 + tid] = acc + pb3[tid];
    } else if (tid >= 32 && tid < 72) {
        int n = tid - 32;
        const float* W = g_wT + 114000 + n;
        float acc = 0.f;
#pragma unroll 8
        for (int k = 0; k < 100; k++) acc = fmaf(sA[100+k], W[k*40], acc);
        g_v[b*40 + n] = acc + vb3[n];
    }
}

// ---------------- PDHG solver (scalar, R6-proven) + fused tail ----------------
struct Co {
    float a24,a25,a26,a27,a28,a29,a2a,a2b;
    float v0,v1,v2,v3,v4,v5;
    float fc0,fc1,fc2,fc3,fc4,fc5;
    float fe0,fe1,fe2,fe3,fe4,fe5,fe6,fe7;
};

__device__ __forceinline__ void amul(const Co& c, const float* s, float* az)
{
    az[0]  = s[4]+s[5]+s[6]+s[7]+s[8]+s[9];
    az[1]  = s[10]+s[11];
    az[2]  = c.a26*s[6] + c.a24*s[4] + c.a27*s[7] + c.a25*s[5]
           + c.a2a*s[10] + c.a28*s[8] + c.a2b*s[11] + c.a29*s[9];
    az[3]  = s[0] - c.v0*s[12] - c.v2*s[14];
    az[4]  = s[2] - c.v1*s[12] - c.v3*s[14];
    az[5]  = s[12] + s[14];
    az[6]  = s[1] - c.v2*s[13] - c.v4*s[15];
    az[7]  = s[3] - c.v3*s[13] - c.v5*s[15];
    az[8]  = s[13] + s[15];
    az[9]  = c.fc0*s[16] + c.fc2*s[18] - s[4];
    az[10] = c.fc1*s[16] + c.fc3*s[18] - s[6];
    az[11] = c.fc2*s[17] + c.fc4*s[19] - s[5];
    az[12] = c.fc3*s[17] + c.fc5*s[19] - s[7];
    az[13] = c.fe0*s[20] + c.fe2*s[21] - s[8];
    az[14] = c.fe1*s[20] + c.fe3*s[21] - s[10];
    az[15] = c.fe4*s[22] + c.fe6*s[23] - s[9];
    az[16] = c.fe5*s[22] + c.fe7*s[23] - s[11];
}

__device__ __forceinline__ void atmul(const Co& c, const float* y, float* g)
{
    g[0]  = y[3];  g[1] = y[6];  g[2] = y[4];  g[3] = y[7];
    g[4]  = y[0] + c.a24*y[2] - y[9];
    g[5]  = y[0] + c.a25*y[2] - y[11];
    g[6]  = y[0] + c.a26*y[2] - y[10];
    g[7]  = y[0] + c.a27*y[2] - y[12];
    g[8]  = y[0] + c.a28*y[2] - y[13];
    g[9]  = y[0] + c.a29*y[2] - y[15];
    g[10] = y[1] + c.a2a*y[2] - y[14];
    g[11] = y[1] + c.a2b*y[2] - y[16];
    g[12] = -c.v0*y[3] - c.v1*y[4] + y[5];
    g[13] = -c.v2*y[6] - c.v3*y[7] + y[8];
    g[14] = -c.v2*y[3] - c.v3*y[4] + y[5];
    g[15] = -c.v4*y[6] - c.v5*y[7] + y[8];
    g[16] = c.fc0*y[9]  + c.fc1*y[10];
    g[17] = c.fc2*y[11] + c.fc3*y[12];
    g[18] = c.fc2*y[9]  + c.fc3*y[10];
    g[19] = c.fc4*y[11] + c.fc5*y[12];
    g[20] = c.fe0*y[13] + c.fe1*y[14];
    g[21] = c.fe2*y[13] + c.fe3*y[14];
    g[22] = c.fe4*y[15] + c.fe5*y[16];
    g[23] = c.fe6*y[15] + c.fe7*y[16];
}

__global__ __launch_bounds__(32) void pdhg_kernel(const float* __restrict__ xtraj,
                                                  const float* __restrict__ x,
                                                  float* __restrict__ out)
{
    int p = blockIdx.x*blockDim.x + threadIdx.x;
    if (p >= NPROB) return;
    int b = p / TT, t = p % TT;
    const float* xt = xtraj + b*45;
    const float* xx = x + b*160;

    float r0 = xt[t], r1 = xt[5+t];
    float ddr0 = xt[30+t], ddr1 = xt[35+t], ddr2 = xt[40+t];

    Co c;
    c.fc0 = xx[20+t]; c.fc1 = xx[25+t]; c.fc2 = xx[30+t];
    c.fc3 = xx[35+t]; c.fc4 = xx[40+t]; c.fc5 = xx[45+t];
    float pe0 = xx[60+t], pe1 = xx[65+t], pe2 = xx[70+t], pe3 = xx[75+t];
    c.fe0 = xx[80+t];  c.fe1 = xx[85+t];  c.fe2 = xx[90+t];  c.fe3 = xx[95+t];
    c.fe4 = xx[100+t]; c.fe5 = xx[105+t]; c.fe6 = xx[110+t]; c.fe7 = xx[115+t];
    const float* vv = g_v + b*40;
    c.v0 = vv[t];    c.v1 = vv[5+t];  c.v2 = vv[10+t];
    c.v3 = vv[15+t]; c.v4 = vv[20+t]; c.v5 = vv[25+t];
    const float* pp = g_pr + b*20;
    float pr0 = pp[t], pr1 = pp[5+t], pr2 = pp[10+t], pr3 = pp[15+t];
    c.a24 = -(pr2 - r1); c.a25 = -(pr3 - r1); c.a26 = pr0 - r0; c.a27 = pr1 - r0;
    c.a28 = -(pe2 - r1); c.a29 = -(pe3 - r1); c.a2a = pe0 - r0; c.a2b = pe1 - r0;

    // ----- spectral norm: 25 power iterations -----
    float u[24];
#pragma unroll
    for (int i = 0; i < 24; i++) u[i] = 1.0f;
    for (int it = 0; it < 25; it++) {
        float w[17], un[24];
        amul(c, u, w);
        atmul(c, w, un);
        float s = 0.0f;
#pragma unroll
        for (int i = 0; i < 24; i++) s += un[i]*un[i];
        float inv = 1.0f/(sqrtf(s) + 1e-12f);
#pragma unroll
        for (int i = 0; i < 24; i++) u[i] = un[i]*inv;
    }
    float w17[17];
    amul(c, u, w17);
    float s = 0.0f;
#pragma unroll
    for (int e = 0; e < 17; e++) s += w17[e]*w17[e];
    float L = sqrtf(s);
    float tau = 0.9f/(L + 1e-8f);
    float sig = tau;

    // ----- PDHG, 400 iterations -----
    float z[24], zb[24], y[17];
#pragma unroll
    for (int i = 0; i < 24; i++) { z[i] = 0.0f; zb[i] = 0.0f; }
#pragma unroll
    for (int e = 0; e < 17; e++) y[e] = 0.0f;

    for (int it = 0; it < 400; it++) {
        float az[17];
        amul(c, zb, az);
        y[0] += sig*(az[0] - ddr0);
        y[1] += sig*(az[1] - ddr1);
        y[2] += sig*(az[2] - ddr2);
        y[3] += sig*az[3];
        y[4] += sig*az[4];
        y[5] += sig*(az[5] - 1.0f);
        y[6] += sig*az[6];
        y[7] += sig*az[7];
        y[8] += sig*(az[8] - 1.0f);
#pragma unroll
        for (int e = 9; e < 17; e++) y[e] += sig*az[e];

        float g[24];
        atmul(c, y, g);
#pragma unroll
        for (int i = 0; i < 24; i++) g[i] = z[i] - tau*g[i];

        float zn[24];
#pragma unroll
        for (int i = 0; i < 4; i++) zn[i] = g[i];
#pragma unroll
        for (int i = 4; i < 8; i++) {
            float a = fabsf(g[i]) - tau;
            zn[i] = (a > 0.0f) ? copysignf(a, g[i]) : 0.0f;
        }
#pragma unroll
        for (int i = 8; i < 12; i++) zn[i] = g[i];
#pragma unroll
        for (int i = 12; i < 24; i++) zn[i] = fmaxf(g[i], 0.0f);
#pragma unroll
        for (int i = 0; i < 24; i++) {
            zb[i] = 2.0f*zn[i] - z[i];
            z[i] = zn[i];
        }
    }

    // ----- write p, f parts (scaled by 100) -----
#pragma unroll
    for (int i = 0; i < 4; i++) out[b*100 + i*5 + t]      = 100.0f * z[i];
#pragma unroll
    for (int i = 0; i < 4; i++) out[b*100 + 20 + i*5 + t] = 100.0f * z[4+i];

    // ----- fused tail: this thread writes 12 of the 60 tail outputs of sample b -----
#pragma unroll
    for (int j = 0; j < 12; j++) {
        int jj = t*12 + j;
        if (jj < 20) out[b*100 + 40 + jj] = 1000.0f*(g_pr[b*20 + jj] - xx[jj]);
        else {
            int k = jj - 20;
            out[b*100 + 60 + k] = 1000.0f*(g_v[b*40 + k] - xx[120 + k]);
        }
    }
}

// ---------------- launch ----------------
extern "C" void kernel_launch(void* const* d_in, const int* in_sizes, int n_in,
                              void* d_out, int out_size)
{
    const float* xtraj = (const float*)d_in[0];
    const float* x     = (const float*)d_in[1];
    const float* x_img = (const float*)d_in[2];
    const float* cw1   = (const float*)d_in[3];
    const float* cb1   = (const float*)d_in[4];
    const float* cw2   = (const float*)d_in[5];
    const float* cb2   = (const float*)d_in[6];
    const float* w3    = (const float*)d_in[7];
    const float* b3    = (const float*)d_in[8];
    const float* w4    = (const float*)d_in[9];
    const float* b4    = (const float*)d_in[10];
    const float* pw1   = (const float*)d_in[11];
    const float* pb1   = (const float*)d_in[12];
    const float* pw2   = (const float*)d_in[13];
    const float* pb2   = (const float*)d_in[14];
    const float* pw3   = (const float*)d_in[15];
    const float* pb3   = (const float*)d_in[16];
    const float* vw1   = (const float*)d_in[17];
    const float* vb1   = (const float*)d_in[18];
    const float* vw2   = (const float*)d_in[19];
    const float* vb2   = (const float*)d_in[20];
    const float* vw3   = (const float*)d_in[21];
    const float* vb3   = (const float*)d_in[22];
    float* out = (float*)d_out;

    transpose_w<<<(118000 + 255)/256, 256>>>(w3, w4, pw1, vw1, pw2, vw2, pw3, vw3);
    conv1_kernel<<<BATCH, 400>>>(x_img, cw1, cb1);
    conv2_kernel<<<BATCH, 320>>>(cw2, cb2);
    mlp_kernel<<<BATCH, 256>>>(xtraj, b3, b4, pb1, vb1, pb2, vb2, pb3, vb3);
    pdhg_kernel<<<(NPROB + 31)/32, 32>>>(xtraj, x, out);
}